// round 5
// baseline (speedup 1.0000x reference)
#include <cuda_runtime.h>
#include <cstdint>
#include <cstddef>

// R5: fix g_W1T size (was 147456 float4 due to operator-order bug; pack kernel
// writes 589824 float4 -> 4x OOB -> illegal memory access in R4).

#define NSAMP 65536
#define DIM   768
#define HID   384
#define NEXP  8
#define NCLS  8
#define TILE_M 128
#define TILE_N 192
#define NCHUNK 2            // 2 x 192 = 384
#define KC    32
#define NKC   (DIM/KC)      // 24
#define THREADS 256
#define MAXTILES 528
#define GRID_TILES 520

// ---- smem layout (bytes) ----
#define SM_ROWIDX 0         // 128 ints = 512
#define SM_B2     512       // 8 floats = 32
#define SM_B1     576       // 384 floats = 1536
#define SM_W2     2112      // 384*8 floats = 12288
#define SM_LP     14400     // 4*128*8 floats = 16384
#define SM_A      30784     // 2 stages * 128*36*4 = 36864
#define SM_B      67648     // 2 stages * 24576 = 49152
#define SM_TOTAL  116800

#define ASTRIDE 36          // floats per A row (pad 32->36: conflict-free frag reads)
#define ABYTES  18432       // 128*36*4
#define BBYTES  24576       // per-chunk B: 2(kg)*24(ntile)*32(lane)*16B

// ---------------- device scratch ----------------
__device__ int    g_counts[NEXP];
__device__ int    g_cursor[NEXP];
__device__ int    g_perm[NSAMP];
__device__ int    g_tile_e[MAXTILES];
__device__ int    g_tile_base[MAXTILES];
__device__ int    g_tile_cnt[MAXTILES];
__device__ int    g_ntiles;
// W1 packed in mma B-fragment order, tf32-rounded:
// [e][nc(2)][kc(24)][kg(2)][ntile(24)][lane(32)] -> float4 {B[k0][n], B[k0+4][n], B[k0+8][n], B[k0+12][n]}
// 8*2*24*1536 = 589824 float4 (9.4 MB)
__device__ float4 g_W1T[589824];

// ---------------- helpers ----------------
__device__ __forceinline__ uint32_t smem_u32(const void* p) {
    uint32_t a;
    asm("{ .reg .u64 t; cvta.to.shared.u64 t, %1; cvt.u32.u64 %0, t; }"
        : "=r"(a) : "l"(p));
    return a;
}
__device__ __forceinline__ uint32_t tf32r(float f) {
    uint32_t r; asm("cvt.rna.tf32.f32 %0, %1;" : "=r"(r) : "f"(f)); return r;
}
__device__ __forceinline__ void cp_async16(uint32_t saddr, const void* g) {
    asm volatile("cp.async.cg.shared.global [%0], [%1], 16;"
                 :: "r"(saddr), "l"(g) : "memory");
}
#define CP_COMMIT() asm volatile("cp.async.commit_group;" ::: "memory")
#define CP_WAIT0()  asm volatile("cp.async.wait_group 0;" ::: "memory")

__device__ __forceinline__ void mma_tf32(float* c, const uint32_t* a,
                                         uint32_t b0, uint32_t b1) {
    asm volatile(
        "mma.sync.aligned.m16n8k8.row.col.f32.tf32.tf32.f32 "
        "{%0,%1,%2,%3}, {%4,%5,%6,%7}, {%8,%9}, {%0,%1,%2,%3};"
        : "+f"(c[0]), "+f"(c[1]), "+f"(c[2]), "+f"(c[3])
        : "r"(a[0]), "r"(a[1]), "r"(a[2]), "r"(a[3]), "r"(b0), "r"(b1));
}

// ---------------- routing ----------------
__global__ void k_zero() {
    if (threadIdx.x < NEXP) g_counts[threadIdx.x] = 0;
}

__global__ void k_hist(const int* __restrict__ qt) {
    __shared__ int h[NEXP];
    if (threadIdx.x < NEXP) h[threadIdx.x] = 0;
    __syncthreads();
    int i = blockIdx.x * blockDim.x + threadIdx.x;
    atomicAdd(&h[qt[i]], 1);
    __syncthreads();
    if (threadIdx.x < NEXP) atomicAdd(&g_counts[threadIdx.x], h[threadIdx.x]);
}

__global__ void k_plan() {
    if (threadIdx.x == 0) {
        int off = 0, nt = 0;
        for (int e = 0; e < NEXP; e++) {
            int c = g_counts[e];
            g_cursor[e] = off;
            int tiles = (c + TILE_M - 1) / TILE_M;
            for (int i = 0; i < tiles; i++) {
                g_tile_e[nt] = e;
                g_tile_base[nt] = off + i * TILE_M;
                int rem = c - i * TILE_M;
                g_tile_cnt[nt] = rem < TILE_M ? rem : TILE_M;
                nt++;
            }
            off += c;
        }
        g_ntiles = nt;
    }
}

__global__ void k_scatter(const int* __restrict__ qt) {
    int i = blockIdx.x * blockDim.x + threadIdx.x;
    int e = qt[i];
    unsigned mask = __match_any_sync(0xffffffffu, e);
    int leader = __ffs(mask) - 1;
    int lane = threadIdx.x & 31;
    int base = 0;
    if (lane == leader) base = atomicAdd(&g_cursor[e], __popc(mask));
    base = __shfl_sync(mask, base, leader);
    int rank = __popc(mask & ((1u << lane) - 1u));
    g_perm[base + rank] = i;
}

// W1[E][D][H] -> fragment-packed g_W1T, tf32-rounded.
// idx -> [e][nc][kc][kg][ntg][lane] (one float4 per thread)
__global__ void k_packW1(const float* __restrict__ W1) {
    int idx = blockIdx.x * 256 + threadIdx.x;          // 0 .. 589823
    int lane = idx & 31;
    int g5   = idx >> 5;
    int ntg  = g5 % 24;
    int kg   = (g5 / 24) % 2;
    int kc   = (g5 / 48) % 24;
    int nc   = (g5 / 1152) % 2;
    int e    = g5 / 2304;
    int n  = nc * TILE_N + ntg * 8 + (lane >> 2);
    int k0 = kc * KC + kg * 16 + (lane & 3);
    const float* src = W1 + (size_t)e * DIM * HID;
    float4 v;
    v.x = __uint_as_float(tf32r(src[(k0 + 0)  * HID + n]));
    v.y = __uint_as_float(tf32r(src[(k0 + 4)  * HID + n]));
    v.z = __uint_as_float(tf32r(src[(k0 + 8)  * HID + n]));
    v.w = __uint_as_float(tf32r(src[(k0 + 12) * HID + n]));
    g_W1T[idx] = v;
}

// ---------------- grouped GEMM (tf32 mma.sync) ----------------
__global__ void __launch_bounds__(THREADS, 1) k_moe(
    const float* __restrict__ x, const float* __restrict__ W2,
    const float* __restrict__ b1, const float* __restrict__ b2,
    float* __restrict__ out)
{
    extern __shared__ char smem[];
    const int tid = threadIdx.x;
    const int t = blockIdx.x;
    if (t >= g_ntiles) return;
    const int lane = tid & 31;
    const int wid  = tid >> 5;
    const int wm = wid & 1;          // 2 m-warps: rows wm*64
    const int wn = wid >> 1;         // 4 n-warps: cols wn*48

    const int e    = g_tile_e[t];
    const int base = g_tile_base[t];
    const int cnt  = g_tile_cnt[t];

    int*   rowidx = (int*)(smem + SM_ROWIDX);
    float* b2s = (float*)(smem + SM_B2);
    float* b1s = (float*)(smem + SM_B1);
    float* w2s = (float*)(smem + SM_W2);
    float* lp  = (float*)(smem + SM_LP);

    // ---- stage constants / indices / zero partials ----
    if (tid < TILE_M) rowidx[tid] = g_perm[base + (tid < cnt ? tid : 0)];
    if (tid < NCLS)   b2s[tid] = b2[e * NCLS + tid];
    {
        const float4* s1 = (const float4*)(b1 + (size_t)e * HID);
        for (int i = tid; i < HID / 4; i += THREADS) ((float4*)b1s)[i] = s1[i];
        const float4* s2 = (const float4*)(W2 + (size_t)e * HID * NCLS);
        for (int i = tid; i < HID * NCLS / 4; i += THREADS) ((float4*)w2s)[i] = s2[i];
        float4 z = make_float4(0.f, 0.f, 0.f, 0.f);
        for (int i = tid; i < 4 * TILE_M * NCLS / 4; i += THREADS) ((float4*)lp)[i] = z;
    }
    __syncthreads();

    const uint32_t sbase = smem_u32(smem);
    const uint32_t bSmem0 = sbase + SM_B;

    // A gather plan: thread -> (row = tid/2, half = tid&1) covers 16 floats/chunk
    const int arow = tid >> 1, ahalf = tid & 1;
    const float* aSrc = x + (size_t)rowidx[arow] * DIM + ahalf * 16;

    for (int nc = 0; nc < NCHUNK; nc++) {
        float acc[4][6][4];
#pragma unroll
        for (int mt = 0; mt < 4; mt++)
#pragma unroll
            for (int nt = 0; nt < 6; nt++)
#pragma unroll
                for (int q = 0; q < 4; q++) acc[mt][nt][q] = 0.f;

        const float4* bChunk = g_W1T + ((size_t)(e * NCHUNK + nc)) * NKC * 1536;

        // ---- prologue: stage chunk 0 ----
        {
            float4 a0[4];
#pragma unroll
            for (int q = 0; q < 4; q++) a0[q] = *(const float4*)(aSrc + q * 4);
            uint32_t* ad = (uint32_t*)(smem + SM_A) + arow * ASTRIDE + ahalf * 16;
#pragma unroll
            for (int q = 0; q < 4; q++) {
                uint4 v = make_uint4(tf32r(a0[q].x), tf32r(a0[q].y),
                                     tf32r(a0[q].z), tf32r(a0[q].w));
                *(uint4*)(ad + q * 4) = v;
            }
            const float4* bs = bChunk + tid;
#pragma unroll
            for (int j = 0; j < 6; j++)
                cp_async16(bSmem0 + (tid + j * 256) * 16, bs + j * 256);
            CP_COMMIT();
        }

        // ---- main K loop ----
        for (int k = 0; k < NKC; k++) {
            const int cur = k & 1, nxt = cur ^ 1;
            CP_WAIT0();          // this thread's B(k) copies done
            __syncthreads();     // everyone's B(k)+A(k) staged; prev-chunk reads done

            float4 aReg[4];
            if (k < NKC - 1) {
                const float4* bs = bChunk + (size_t)(k + 1) * 1536 + tid;
#pragma unroll
                for (int j = 0; j < 6; j++)
                    cp_async16(bSmem0 + nxt * BBYTES + (tid + j * 256) * 16,
                               bs + j * 256);
                CP_COMMIT();
#pragma unroll
                for (int q = 0; q < 4; q++)
                    aReg[q] = *(const float4*)(aSrc + (k + 1) * KC + q * 4);
            }

            // compute chunk k
            const uint32_t* As = (const uint32_t*)(smem + SM_A + cur * ABYTES);
            const uint4*    Bs = (const uint4*)(smem + SM_B + cur * BBYTES);
#pragma unroll
            for (int kg = 0; kg < 2; kg++) {
                uint4 bf[6];
#pragma unroll
                for (int nt = 0; nt < 6; nt++)
                    bf[nt] = Bs[(kg * 24 + wn * 6 + nt) * 32 + lane];
#pragma unroll
                for (int ks = 0; ks < 2; ks++) {
                    const int col = (kg * 2 + ks) * 8 + (lane & 3);
                    uint32_t af[4][4];
#pragma unroll
                    for (int mt = 0; mt < 4; mt++) {
                        const int row = wm * 64 + mt * 16 + (lane >> 2);
                        af[mt][0] = As[row * ASTRIDE + col];
                        af[mt][1] = As[(row + 8) * ASTRIDE + col];
                        af[mt][2] = As[row * ASTRIDE + col + 4];
                        af[mt][3] = As[(row + 8) * ASTRIDE + col + 4];
                    }
#pragma unroll
                    for (int mt = 0; mt < 4; mt++)
#pragma unroll
                        for (int nt = 0; nt < 6; nt++)
                            mma_tf32(acc[mt][nt], af[mt],
                                     ks ? bf[nt].z : bf[nt].x,
                                     ks ? bf[nt].w : bf[nt].y);
                }
            }

            if (k < NKC - 1) {   // stage A(k+1) into nxt
                uint32_t* ad = (uint32_t*)(smem + SM_A + nxt * ABYTES)
                               + arow * ASTRIDE + ahalf * 16;
#pragma unroll
                for (int q = 0; q < 4; q++) {
                    uint4 v = make_uint4(tf32r(aReg[q].x), tf32r(aReg[q].y),
                                         tf32r(aReg[q].z), tf32r(aReg[q].w));
                    *(uint4*)(ad + q * 4) = v;
                }
            }
        }

        // ---- layer-2 partials from accumulators ----
#pragma unroll
        for (int mt = 0; mt < 4; mt++) {
            float p[2][8];
#pragma unroll
            for (int rr = 0; rr < 2; rr++)
#pragma unroll
                for (int c = 0; c < 8; c++) p[rr][c] = 0.f;
#pragma unroll
            for (int nt = 0; nt < 6; nt++) {
                const int ng = nc * TILE_N + wn * 48 + nt * 8 + (lane & 3) * 2;
                const float bb0 = b1s[ng], bb1 = b1s[ng + 1];
                const float4* w0 = (const float4*)(w2s + ng * 8);
                const float4 wa0 = w0[0], wa1 = w0[1], wb0 = w0[2], wb1 = w0[3];
                const float h00 = fmaxf(acc[mt][nt][0] + bb0, 0.f);
                const float h01 = fmaxf(acc[mt][nt][1] + bb1, 0.f);
                const float h10 = fmaxf(acc[mt][nt][2] + bb0, 0.f);
                const float h11 = fmaxf(acc[mt][nt][3] + bb1, 0.f);
                p[0][0] = fmaf(h00, wa0.x, fmaf(h01, wb0.x, p[0][0]));
                p[0][1] = fmaf(h00, wa0.y, fmaf(h01, wb0.y, p[0][1]));
                p[0][2] = fmaf(h00, wa0.z, fmaf(h01, wb0.z, p[0][2]));
                p[0][3] = fmaf(h00, wa0.w, fmaf(h01, wb0.w, p[0][3]));
                p[0][4] = fmaf(h00, wa1.x, fmaf(h01, wb1.x, p[0][4]));
                p[0][5] = fmaf(h00, wa1.y, fmaf(h01, wb1.y, p[0][5]));
                p[0][6] = fmaf(h00, wa1.z, fmaf(h01, wb1.z, p[0][6]));
                p[0][7] = fmaf(h00, wa1.w, fmaf(h01, wb1.w, p[0][7]));
                p[1][0] = fmaf(h10, wa0.x, fmaf(h11, wb0.x, p[1][0]));
                p[1][1] = fmaf(h10, wa0.y, fmaf(h11, wb0.y, p[1][1]));
                p[1][2] = fmaf(h10, wa0.z, fmaf(h11, wb0.z, p[1][2]));
                p[1][3] = fmaf(h10, wa0.w, fmaf(h11, wb0.w, p[1][3]));
                p[1][4] = fmaf(h10, wa1.x, fmaf(h11, wb1.x, p[1][4]));
                p[1][5] = fmaf(h10, wa1.y, fmaf(h11, wb1.y, p[1][5]));
                p[1][6] = fmaf(h10, wa1.z, fmaf(h11, wb1.z, p[1][6]));
                p[1][7] = fmaf(h10, wa1.w, fmaf(h11, wb1.w, p[1][7]));
            }
            // reduce across the 4 lanes of each quad (they share rows, differ in n)
#pragma unroll
            for (int rr = 0; rr < 2; rr++)
#pragma unroll
                for (int c = 0; c < 8; c++) {
                    float v = p[rr][c];
                    v += __shfl_xor_sync(0xffffffffu, v, 1);
                    v += __shfl_xor_sync(0xffffffffu, v, 2);
                    p[rr][c] = v;
                }
            if ((lane & 3) == 0) {
#pragma unroll
                for (int rr = 0; rr < 2; rr++) {
                    const int row = wm * 64 + mt * 16 + rr * 8 + (lane >> 2);
                    float* dst = lp + ((size_t)wn * TILE_M + row) * 8;
#pragma unroll
                    for (int c = 0; c < 8; c++) dst[c] += p[rr][c];
                }
            }
        }
    }

    // ---- combine n-warp partials + b2, scatter ----
    __syncthreads();
    if (tid < TILE_M && tid < cnt) {
        float o[8];
#pragma unroll
        for (int c = 0; c < 8; c++)
            o[c] = lp[(0 * TILE_M + tid) * 8 + c] + lp[(1 * TILE_M + tid) * 8 + c]
                 + lp[(2 * TILE_M + tid) * 8 + c] + lp[(3 * TILE_M + tid) * 8 + c]
                 + b2s[c];
        float4* dst = (float4*)(out + (size_t)rowidx[tid] * NCLS);
        dst[0] = make_float4(o[0], o[1], o[2], o[3]);
        dst[1] = make_float4(o[4], o[5], o[6], o[7]);
    }
}

// ---------------- launch ----------------
extern "C" void kernel_launch(void* const* d_in, const int* in_sizes, int n_in,
                              void* d_out, int out_size) {
    const float* x = nullptr;
    const float* W1 = nullptr;
    const float* b1 = nullptr;
    const float* W2 = nullptr;
    const float* b2 = nullptr;
    const int* qt = nullptr;
    for (int i = 0; i < n_in; i++) {
        switch (in_sizes[i]) {
            case NSAMP * DIM:       x  = (const float*)d_in[i]; break;
            case NEXP * DIM * HID:  W1 = (const float*)d_in[i]; break;
            case NEXP * HID:        b1 = (const float*)d_in[i]; break;
            case NEXP * HID * NCLS: W2 = (const float*)d_in[i]; break;
            case NEXP * NCLS:       b2 = (const float*)d_in[i]; break;
            case NSAMP:             qt = (const int*)d_in[i];   break;
            default: break;
        }
    }
    float* out = (float*)d_out;

    k_zero<<<1, 32>>>();
    k_hist<<<NSAMP / 256, 256>>>(qt);
    k_plan<<<1, 32>>>();
    k_scatter<<<NSAMP / 256, 256>>>(qt);
    k_packW1<<<(NEXP * NCHUNK * NKC * 1536) / 256, 256>>>(W1);

    cudaFuncSetAttribute(k_moe, cudaFuncAttributeMaxDynamicSharedMemorySize,
                         SM_TOTAL);
    k_moe<<<GRID_TILES, THREADS, SM_TOTAL>>>(x, W2, b1, b2, out);
}

// round 7
// speedup vs baseline: 1.1845x; 1.1845x over previous
#include <cuda_runtime.h>
#include <cuda_fp16.h>
#include <cstdint>
#include <cstddef>

// R7: resubmission of R6 (container flake gave no signal). fp16 m16n8k16
// GEMM1 (same mantissa as tf32 => same error), fp32 layer-2 epilogue.

#define NSAMP 65536
#define DIM   768
#define HID   384
#define NEXP  8
#define NCLS  8
#define TILE_M 128
#define TILE_N 192
#define NCHUNK 2            // 2 x 192 = 384
#define KC    64
#define NKC   (DIM/KC)      // 12
#define THREADS 256
#define MAXTILES 528
#define GRID_TILES 520

// ---- smem layout (bytes) ----
#define SM_ROWIDX 0         // 128 ints = 512
#define SM_B2     512       // 8 floats = 32
#define SM_B1     576       // 384 floats = 1536
#define SM_W2     2112      // 384*8 floats = 12288
#define SM_LP     14400     // 4*128*8 floats = 16384
#define SM_A      30784     // 2 stages * 128*36*4 = 36864 (36 b32 = 72 halves/row)
#define SM_B      67648     // 2 stages * 24576 = 49152
#define SM_TOTAL  116800

#define AST32   36          // b32 per A row (32 data + 4 pad: conflict-free)
#define ABYTES  18432       // 128*36*4
#define BBYTES  24576       // per-chunk B: 4(kstep)*24(ntile)*32(lane)*8B

// ---------------- device scratch ----------------
__device__ int    g_counts[NEXP];
__device__ int    g_cursor[NEXP];
__device__ int    g_perm[NSAMP];
__device__ int    g_tile_e[MAXTILES];
__device__ int    g_tile_base[MAXTILES];
__device__ int    g_tile_cnt[MAXTILES];
__device__ int    g_ntiles;
// W1 packed as fp16 mma B-fragments:
// [e][nc(2)][kc(12)][kstep(4)][ntile(24)][lane(32)] -> uint2 {b0,b1}
// b0 = half2(W[k0][n], W[k0+1][n]); b1 = half2(W[k0+8][n], W[k0+9][n])
// 8*2*12*4*24*32 = 589824 uint2 (4.7 MB)
__device__ uint2 g_W1T[589824];

// ---------------- helpers ----------------
__device__ __forceinline__ uint32_t smem_u32(const void* p) {
    uint32_t a;
    asm("{ .reg .u64 t; cvta.to.shared.u64 t, %1; cvt.u32.u64 %0, t; }"
        : "=r"(a) : "l"(p));
    return a;
}
__device__ __forceinline__ uint32_t pack2(float a, float b) {
    __half2 h = __floats2half2_rn(a, b);    // .x = a (low), .y = b (high)
    return *reinterpret_cast<uint32_t*>(&h);
}
__device__ __forceinline__ void cp_async16(uint32_t saddr, const void* g) {
    asm volatile("cp.async.cg.shared.global [%0], [%1], 16;"
                 :: "r"(saddr), "l"(g) : "memory");
}
#define CP_COMMIT() asm volatile("cp.async.commit_group;" ::: "memory")
#define CP_WAIT0()  asm volatile("cp.async.wait_group 0;" ::: "memory")

__device__ __forceinline__ void mma_f16(float* c, const uint32_t* a,
                                        uint32_t b0, uint32_t b1) {
    asm volatile(
        "mma.sync.aligned.m16n8k16.row.col.f32.f16.f16.f32 "
        "{%0,%1,%2,%3}, {%4,%5,%6,%7}, {%8,%9}, {%0,%1,%2,%3};"
        : "+f"(c[0]), "+f"(c[1]), "+f"(c[2]), "+f"(c[3])
        : "r"(a[0]), "r"(a[1]), "r"(a[2]), "r"(a[3]), "r"(b0), "r"(b1));
}

// ---------------- routing ----------------
__global__ void k_zero() {
    if (threadIdx.x < NEXP) g_counts[threadIdx.x] = 0;
}

__global__ void k_hist(const int* __restrict__ qt) {
    __shared__ int h[NEXP];
    if (threadIdx.x < NEXP) h[threadIdx.x] = 0;
    __syncthreads();
    int i = blockIdx.x * blockDim.x + threadIdx.x;
    atomicAdd(&h[qt[i]], 1);
    __syncthreads();
    if (threadIdx.x < NEXP) atomicAdd(&g_counts[threadIdx.x], h[threadIdx.x]);
}

__global__ void k_plan() {
    if (threadIdx.x == 0) {
        int off = 0, nt = 0;
        for (int e = 0; e < NEXP; e++) {
            int c = g_counts[e];
            g_cursor[e] = off;
            int tiles = (c + TILE_M - 1) / TILE_M;
            for (int i = 0; i < tiles; i++) {
                g_tile_e[nt] = e;
                g_tile_base[nt] = off + i * TILE_M;
                int rem = c - i * TILE_M;
                g_tile_cnt[nt] = rem < TILE_M ? rem : TILE_M;
                nt++;
            }
            off += c;
        }
        g_ntiles = nt;
    }
}

__global__ void k_scatter(const int* __restrict__ qt) {
    int i = blockIdx.x * blockDim.x + threadIdx.x;
    int e = qt[i];
    unsigned mask = __match_any_sync(0xffffffffu, e);
    int leader = __ffs(mask) - 1;
    int lane = threadIdx.x & 31;
    int base = 0;
    if (lane == leader) base = atomicAdd(&g_cursor[e], __popc(mask));
    base = __shfl_sync(mask, base, leader);
    int rank = __popc(mask & ((1u << lane) - 1u));
    g_perm[base + rank] = i;
}

// W1[E][D][H] -> fp16 fragment-packed g_W1T
__global__ void k_packW1(const float* __restrict__ W1) {
    int idx = blockIdx.x * 256 + threadIdx.x;          // 0 .. 589823
    int lane = idx & 31;
    int g5   = idx >> 5;
    int ntg  = g5 % 24;
    int ks   = (g5 / 24) % 4;
    int kc   = (g5 / 96) % 12;
    int nc   = (g5 / 1152) % 2;
    int e    = g5 / 2304;
    int n  = nc * TILE_N + ntg * 8 + (lane >> 2);
    int k0 = kc * KC + ks * 16 + 2 * (lane & 3);
    const float* src = W1 + (size_t)e * DIM * HID;
    uint2 v;
    v.x = pack2(src[(k0 + 0) * HID + n], src[(k0 + 1) * HID + n]);
    v.y = pack2(src[(k0 + 8) * HID + n], src[(k0 + 9) * HID + n]);
    g_W1T[idx] = v;
}

// ---------------- grouped GEMM (fp16 mma.sync) ----------------
__global__ void __launch_bounds__(THREADS, 1) k_moe(
    const float* __restrict__ x, const float* __restrict__ W2,
    const float* __restrict__ b1, const float* __restrict__ b2,
    float* __restrict__ out)
{
    extern __shared__ char smem[];
    const int tid = threadIdx.x;
    const int t = blockIdx.x;
    if (t >= g_ntiles) return;
    const int lane = tid & 31;
    const int wid  = tid >> 5;
    const int wm = wid & 1;          // 2 m-warps: rows wm*64
    const int wn = wid >> 1;         // 4 n-warps: cols wn*48

    const int e    = g_tile_e[t];
    const int base = g_tile_base[t];
    const int cnt  = g_tile_cnt[t];

    int*   rowidx = (int*)(smem + SM_ROWIDX);
    float* b2s = (float*)(smem + SM_B2);
    float* b1s = (float*)(smem + SM_B1);
    float* w2s = (float*)(smem + SM_W2);
    float* lp  = (float*)(smem + SM_LP);

    // ---- stage constants / indices / zero partials ----
    if (tid < TILE_M) rowidx[tid] = g_perm[base + (tid < cnt ? tid : 0)];
    if (tid < NCLS)   b2s[tid] = b2[e * NCLS + tid];
    {
        const float4* s1 = (const float4*)(b1 + (size_t)e * HID);
        for (int i = tid; i < HID / 4; i += THREADS) ((float4*)b1s)[i] = s1[i];
        const float4* s2 = (const float4*)(W2 + (size_t)e * HID * NCLS);
        for (int i = tid; i < HID * NCLS / 4; i += THREADS) ((float4*)w2s)[i] = s2[i];
        float4 z = make_float4(0.f, 0.f, 0.f, 0.f);
        for (int i = tid; i < 4 * TILE_M * NCLS / 4; i += THREADS) ((float4*)lp)[i] = z;
    }
    __syncthreads();

    const uint32_t sbase = smem_u32(smem);
    const uint32_t bSmem0 = sbase + SM_B;

    // A gather plan: thread -> (row = tid/2, half = tid&1): 32 floats/chunk
    const int arow = tid >> 1, ahalf = tid & 1;
    const float* aSrc = x + (size_t)rowidx[arow] * DIM + ahalf * 32;

    for (int nc = 0; nc < NCHUNK; nc++) {
        float acc[4][6][4];
#pragma unroll
        for (int mt = 0; mt < 4; mt++)
#pragma unroll
            for (int nt = 0; nt < 6; nt++)
#pragma unroll
                for (int q = 0; q < 4; q++) acc[mt][nt][q] = 0.f;

        const uint2* bChunk = g_W1T + ((size_t)(e * NCHUNK + nc)) * NKC * 3072;

        // ---- prologue: stage chunk 0 into buffer 0 ----
        {
            const uint2* bs = bChunk + tid * 2;
#pragma unroll
            for (int j = 0; j < 6; j++)
                cp_async16(bSmem0 + (tid + j * 256) * 16, bs + j * 512);
            CP_COMMIT();
            uint32_t* ad = (uint32_t*)(smem + SM_A) + arow * AST32 + ahalf * 16;
#pragma unroll
            for (int q = 0; q < 4; q++) {
                float4 fa = *(const float4*)(aSrc + q * 8);
                float4 fb = *(const float4*)(aSrc + q * 8 + 4);
                uint4 v = make_uint4(pack2(fa.x, fa.y), pack2(fa.z, fa.w),
                                     pack2(fb.x, fb.y), pack2(fb.z, fb.w));
                *(uint4*)(ad + q * 4) = v;
            }
        }

        // ---- main K loop ----
        for (int k = 0; k < NKC; k++) {
            const int cur = k & 1, nxt = cur ^ 1;
            CP_WAIT0();          // B(k) copies landed
            __syncthreads();     // all stages visible; prev-chunk reads done

            if (k < NKC - 1) {
                const uint2* bs = bChunk + (size_t)(k + 1) * 3072 + tid * 2;
#pragma unroll
                for (int j = 0; j < 6; j++)
                    cp_async16(bSmem0 + nxt * BBYTES + (tid + j * 256) * 16,
                               bs + j * 512);
                CP_COMMIT();
                // A(k+1): gather -> fp16 -> stage into nxt (nxt not read now)
                const float* as = aSrc + (k + 1) * KC;
                uint32_t* ad = (uint32_t*)(smem + SM_A + nxt * ABYTES)
                               + arow * AST32 + ahalf * 16;
#pragma unroll
                for (int q = 0; q < 4; q++) {
                    float4 fa = *(const float4*)(as + q * 8);
                    float4 fb = *(const float4*)(as + q * 8 + 4);
                    uint4 v = make_uint4(pack2(fa.x, fa.y), pack2(fa.z, fa.w),
                                         pack2(fb.x, fb.y), pack2(fb.z, fb.w));
                    *(uint4*)(ad + q * 4) = v;
                }
            }

            // compute chunk k (K=64 = 4 ksteps of 16)
            const uint32_t* As = (const uint32_t*)(smem + SM_A + cur * ABYTES);
            const uint2*    Bs = (const uint2*)(smem + SM_B + cur * BBYTES);
#pragma unroll
            for (int ks = 0; ks < 4; ks++) {
                uint2 bf[6];
#pragma unroll
                for (int nt = 0; nt < 6; nt++)
                    bf[nt] = Bs[(ks * 24 + wn * 6 + nt) * 32 + lane];
                const int col = ks * 8 + (lane & 3);
                uint32_t af[4][4];
#pragma unroll
                for (int mt = 0; mt < 4; mt++) {
                    const int row = wm * 64 + mt * 16 + (lane >> 2);
                    af[mt][0] = As[row * AST32 + col];
                    af[mt][1] = As[(row + 8) * AST32 + col];
                    af[mt][2] = As[row * AST32 + col + 4];
                    af[mt][3] = As[(row + 8) * AST32 + col + 4];
                }
#pragma unroll
                for (int mt = 0; mt < 4; mt++)
#pragma unroll
                    for (int nt = 0; nt < 6; nt++)
                        mma_f16(acc[mt][nt], af[mt], bf[nt].x, bf[nt].y);
            }
        }

        // ---- layer-2 partials from accumulators (fp32) ----
#pragma unroll
        for (int mt = 0; mt < 4; mt++) {
            float p[2][8];
#pragma unroll
            for (int rr = 0; rr < 2; rr++)
#pragma unroll
                for (int c = 0; c < 8; c++) p[rr][c] = 0.f;
#pragma unroll
            for (int nt = 0; nt < 6; nt++) {
                const int ng = nc * TILE_N + wn * 48 + nt * 8 + (lane & 3) * 2;
                const float bb0 = b1s[ng], bb1 = b1s[ng + 1];
                const float4* w0 = (const float4*)(w2s + ng * 8);
                const float4 wa0 = w0[0], wa1 = w0[1], wb0 = w0[2], wb1 = w0[3];
                const float h00 = fmaxf(acc[mt][nt][0] + bb0, 0.f);
                const float h01 = fmaxf(acc[mt][nt][1] + bb1, 0.f);
                const float h10 = fmaxf(acc[mt][nt][2] + bb0, 0.f);
                const float h11 = fmaxf(acc[mt][nt][3] + bb1, 0.f);
                p[0][0] = fmaf(h00, wa0.x, fmaf(h01, wb0.x, p[0][0]));
                p[0][1] = fmaf(h00, wa0.y, fmaf(h01, wb0.y, p[0][1]));
                p[0][2] = fmaf(h00, wa0.z, fmaf(h01, wb0.z, p[0][2]));
                p[0][3] = fmaf(h00, wa0.w, fmaf(h01, wb0.w, p[0][3]));
                p[0][4] = fmaf(h00, wa1.x, fmaf(h01, wb1.x, p[0][4]));
                p[0][5] = fmaf(h00, wa1.y, fmaf(h01, wb1.y, p[0][5]));
                p[0][6] = fmaf(h00, wa1.z, fmaf(h01, wb1.z, p[0][6]));
                p[0][7] = fmaf(h00, wa1.w, fmaf(h01, wb1.w, p[0][7]));
                p[1][0] = fmaf(h10, wa0.x, fmaf(h11, wb0.x, p[1][0]));
                p[1][1] = fmaf(h10, wa0.y, fmaf(h11, wb0.y, p[1][1]));
                p[1][2] = fmaf(h10, wa0.z, fmaf(h11, wb0.z, p[1][2]));
                p[1][3] = fmaf(h10, wa0.w, fmaf(h11, wb0.w, p[1][3]));
                p[1][4] = fmaf(h10, wa1.x, fmaf(h11, wb1.x, p[1][4]));
                p[1][5] = fmaf(h10, wa1.y, fmaf(h11, wb1.y, p[1][5]));
                p[1][6] = fmaf(h10, wa1.z, fmaf(h11, wb1.z, p[1][6]));
                p[1][7] = fmaf(h10, wa1.w, fmaf(h11, wb1.w, p[1][7]));
            }
            // reduce across the 4 lanes of each quad
#pragma unroll
            for (int rr = 0; rr < 2; rr++)
#pragma unroll
                for (int c = 0; c < 8; c++) {
                    float v = p[rr][c];
                    v += __shfl_xor_sync(0xffffffffu, v, 1);
                    v += __shfl_xor_sync(0xffffffffu, v, 2);
                    p[rr][c] = v;
                }
            if ((lane & 3) == 0) {
#pragma unroll
                for (int rr = 0; rr < 2; rr++) {
                    const int row = wm * 64 + mt * 16 + rr * 8 + (lane >> 2);
                    float* dst = lp + ((size_t)wn * TILE_M + row) * 8;
#pragma unroll
                    for (int c = 0; c < 8; c++) dst[c] += p[rr][c];
                }
            }
        }
    }

    // ---- combine n-warp partials + b2, scatter ----
    __syncthreads();
    if (tid < TILE_M && tid < cnt) {
        float o[8];
#pragma unroll
        for (int c = 0; c < 8; c++)
            o[c] = lp[(0 * TILE_M + tid) * 8 + c] + lp[(1 * TILE_M + tid) * 8 + c]
                 + lp[(2 * TILE_M + tid) * 8 + c] + lp[(3 * TILE_M + tid) * 8 + c]
                 + b2s[c];
        float4* dst = (float4*)(out + (size_t)rowidx[tid] * NCLS);
        dst[0] = make_float4(o[0], o[1], o[2], o[3]);
        dst[1] = make_float4(o[4], o[5], o[6], o[7]);
    }
}

// ---------------- launch ----------------
extern "C" void kernel_launch(void* const* d_in, const int* in_sizes, int n_in,
                              void* d_out, int out_size) {
    const float* x = nullptr;
    const float* W1 = nullptr;
    const float* b1 = nullptr;
    const float* W2 = nullptr;
    const float* b2 = nullptr;
    const int* qt = nullptr;
    for (int i = 0; i < n_in; i++) {
        switch (in_sizes[i]) {
            case NSAMP * DIM:       x  = (const float*)d_in[i]; break;
            case NEXP * DIM * HID:  W1 = (const float*)d_in[i]; break;
            case NEXP * HID:        b1 = (const float*)d_in[i]; break;
            case NEXP * HID * NCLS: W2 = (const float*)d_in[i]; break;
            case NEXP * NCLS:       b2 = (const float*)d_in[i]; break;
            case NSAMP:             qt = (const int*)d_in[i];   break;
            default: break;
        }
    }
    float* out = (float*)d_out;

    k_zero<<<1, 32>>>();
    k_hist<<<NSAMP / 256, 256>>>(qt);
    k_plan<<<1, 32>>>();
    k_scatter<<<NSAMP / 256, 256>>>(qt);
    k_packW1<<<(8 * 2 * 12 * 4 * 24 * 32) / 256, 256>>>(W1);

    cudaFuncSetAttribute(k_moe, cudaFuncAttributeMaxDynamicSharedMemorySize,
                         SM_TOTAL);
    k_moe<<<GRID_TILES, THREADS, SM_TOTAL>>>(x, W2, b1, b2, out);
}

// round 8
// speedup vs baseline: 1.3697x; 1.1564x over previous
#include <cuda_runtime.h>
#include <cuda_fp16.h>
#include <cstdint>
#include <cstddef>

// R8: overhead attack. ldmatrix.x4 A-frags (16 LDS.32 -> 4 LDSM), paired-uint4
// B frags (6 LDS.64 -> 3 LDS.128), A pack/STS deferred until after compute
// (LDG latency hidden behind mma), 4-kernel launch list (plan folded into
// scatter/moe via in-kernel prefix over 8 expert counts).

#define NSAMP 65536
#define DIM   768
#define HID   384
#define NEXP  8
#define NCLS  8
#define TILE_M 128
#define TILE_N 192
#define NCHUNK 2            // 2 x 192 = 384
#define KC    64
#define NKC   (DIM/KC)      // 12
#define THREADS 256
#define GRID_TILES 520

// ---- smem layout (bytes) ----
#define SM_ROWIDX 0         // 128 ints = 512
#define SM_B2     512       // 8 floats = 32
#define SM_B1     576       // 384 floats = 1536
#define SM_W2     2112      // 384*8 floats = 12288
#define SM_LP     14400     // 4*128*8 floats = 16384
#define SM_A      30784     // 2 stages * 128*36*4 = 36864 (36 b32 = 72 halves/row)
#define SM_B      67648     // 2 stages * 24576 = 49152
#define SM_TOTAL  116800

#define AST32   36          // b32 per A row (32 data + 4 pad)
#define AROWB   144         // bytes per A row
#define ABYTES  18432       // 128*144
#define BBYTES  24576       // per-chunk B: 4(ks)*12(ntp)*32(lane)*16B

// ---------------- device scratch ----------------
__device__ int    g_cnt[2 * NEXP];   // [0..7]=counts, [8..15]=fill cursors
__device__ int    g_perm[NSAMP];
// W1 packed as paired fp16 mma B-fragments:
// [e][nc(2)][kc(12)][ks(4)][ntp(12)][lane(32)] -> uint4
// .x = half2(W[k0][n0],W[k0+1][n0])   .y = half2(W[k0+8][n0],W[k0+9][n0])
// .z,.w same for n1 = n0+8.   8*2*12*4*12*32 = 294912 uint4 (4.7 MB)
__device__ uint4 g_W1T[294912];

// ---------------- helpers ----------------
__device__ __forceinline__ uint32_t smem_u32(const void* p) {
    uint32_t a;
    asm("{ .reg .u64 t; cvta.to.shared.u64 t, %1; cvt.u32.u64 %0, t; }"
        : "=r"(a) : "l"(p));
    return a;
}
__device__ __forceinline__ uint32_t pack2(float a, float b) {
    __half2 h = __floats2half2_rn(a, b);
    return *reinterpret_cast<uint32_t*>(&h);
}
__device__ __forceinline__ void cp_async16(uint32_t saddr, const void* g) {
    asm volatile("cp.async.cg.shared.global [%0], [%1], 16;"
                 :: "r"(saddr), "l"(g) : "memory");
}
#define CP_COMMIT() asm volatile("cp.async.commit_group;" ::: "memory")
#define CP_WAIT0()  asm volatile("cp.async.wait_group 0;" ::: "memory")

__device__ __forceinline__ void ldsm4(uint32_t* r, uint32_t addr) {
    asm volatile("ldmatrix.sync.aligned.m8n8.x4.shared.b16 {%0,%1,%2,%3}, [%4];"
                 : "=r"(r[0]), "=r"(r[1]), "=r"(r[2]), "=r"(r[3]) : "r"(addr));
}
__device__ __forceinline__ void mma_f16(float* c, const uint32_t* a,
                                        uint32_t b0, uint32_t b1) {
    asm volatile(
        "mma.sync.aligned.m16n8k16.row.col.f32.f16.f16.f32 "
        "{%0,%1,%2,%3}, {%4,%5,%6,%7}, {%8,%9}, {%0,%1,%2,%3};"
        : "+f"(c[0]), "+f"(c[1]), "+f"(c[2]), "+f"(c[3])
        : "r"(a[0]), "r"(a[1]), "r"(a[2]), "r"(a[3]), "r"(b0), "r"(b1));
}

// ---------------- routing ----------------
__global__ void k_hist(const int* __restrict__ qt) {
    __shared__ int h[NEXP];
    if (threadIdx.x < NEXP) h[threadIdx.x] = 0;
    __syncthreads();
    int i = blockIdx.x * blockDim.x + threadIdx.x;
    atomicAdd(&h[qt[i]], 1);
    __syncthreads();
    if (threadIdx.x < NEXP) atomicAdd(&g_cnt[threadIdx.x], h[threadIdx.x]);
}

// scatter computes expert prefix in-register from g_cnt[0..7]
__global__ void k_scatter(const int* __restrict__ qt) {
    int i = blockIdx.x * blockDim.x + threadIdx.x;
    int e = qt[i];
    int off = 0;
#pragma unroll
    for (int j = 0; j < NEXP; j++) {
        int cj = g_cnt[j];
        off += (j < e) ? cj : 0;
    }
    unsigned mask = __match_any_sync(0xffffffffu, e);
    int leader = __ffs(mask) - 1;
    int lane = threadIdx.x & 31;
    int base = 0;
    if (lane == leader) base = atomicAdd(&g_cnt[NEXP + e], __popc(mask));
    base = __shfl_sync(mask, base, leader);
    int rank = __popc(mask & ((1u << lane) - 1u));
    g_perm[off + base + rank] = i;
}

// W1[E][D][H] -> paired fp16 fragment pack
__global__ void k_packW1(const float* __restrict__ W1) {
    int idx = blockIdx.x * 256 + threadIdx.x;          // 0 .. 294911
    int lane = idx & 31;
    int g5   = idx >> 5;
    int ntp  = g5 % 12;
    int ks   = (g5 / 12) % 4;
    int kc   = (g5 / 48) % 12;
    int nc   = (g5 / 576) % 2;
    int e    = g5 / 1152;
    int n0 = nc * TILE_N + ntp * 16 + (lane >> 2);
    int k0 = kc * KC + ks * 16 + 2 * (lane & 3);
    const float* src = W1 + (size_t)e * DIM * HID;
    uint4 v;
    v.x = pack2(src[(k0 + 0) * HID + n0], src[(k0 + 1) * HID + n0]);
    v.y = pack2(src[(k0 + 8) * HID + n0], src[(k0 + 9) * HID + n0]);
    v.z = pack2(src[(k0 + 0) * HID + n0 + 8], src[(k0 + 1) * HID + n0 + 8]);
    v.w = pack2(src[(k0 + 8) * HID + n0 + 8], src[(k0 + 9) * HID + n0 + 8]);
    g_W1T[idx] = v;
}

// ---------------- grouped GEMM (fp16 mma.sync + ldmatrix) ----------------
__global__ void __launch_bounds__(THREADS, 1) k_moe(
    const float* __restrict__ x, const float* __restrict__ W2,
    const float* __restrict__ b1, const float* __restrict__ b2,
    float* __restrict__ out)
{
    extern __shared__ char smem[];
    const int tid = threadIdx.x;
    const int t = blockIdx.x;
    const int lane = tid & 31;
    const int wid  = tid >> 5;
    const int wm = wid & 1;          // 2 m-warps: rows wm*64
    const int wn = wid >> 1;         // 4 n-warps: cols wn*48

    // ---- derive (e, base, cnt) from counts prefix (no tile tables) ----
    int e = -1, base = 0, cnt = 0;
    {
        int off = 0, tacc = 0;
#pragma unroll
        for (int e0 = 0; e0 < NEXP; e0++) {
            int c = g_cnt[e0];
            int tiles = (c + TILE_M - 1) >> 7;
            if (e < 0 && t >= tacc && t < tacc + tiles) {
                int local = t - tacc;
                e = e0;
                base = off + local * TILE_M;
                int rem = c - local * TILE_M;
                cnt = rem < TILE_M ? rem : TILE_M;
            }
            tacc += tiles;
            off += c;
        }
        if (e < 0) return;   // t >= ntiles (uniform per CTA)
    }

    int*   rowidx = (int*)(smem + SM_ROWIDX);
    float* b2s = (float*)(smem + SM_B2);
    float* b1s = (float*)(smem + SM_B1);
    float* w2s = (float*)(smem + SM_W2);
    float* lp  = (float*)(smem + SM_LP);

    // ---- stage constants / indices / zero partials ----
    if (tid < TILE_M) rowidx[tid] = g_perm[base + (tid < cnt ? tid : 0)];
    if (tid < NCLS)   b2s[tid] = b2[e * NCLS + tid];
    {
        const float4* s1 = (const float4*)(b1 + (size_t)e * HID);
        for (int i = tid; i < HID / 4; i += THREADS) ((float4*)b1s)[i] = s1[i];
        const float4* s2 = (const float4*)(W2 + (size_t)e * HID * NCLS);
        for (int i = tid; i < HID * NCLS / 4; i += THREADS) ((float4*)w2s)[i] = s2[i];
        float4 z = make_float4(0.f, 0.f, 0.f, 0.f);
        for (int i = tid; i < 4 * TILE_M * NCLS / 4; i += THREADS) ((float4*)lp)[i] = z;
    }
    __syncthreads();

    const uint32_t sbase = smem_u32(smem);
    const uint32_t bSmem0 = sbase + SM_B;

    // A gather plan: thread -> (row = tid/2, half = tid&1): 32 floats/chunk
    const int arow = tid >> 1, ahalf = tid & 1;
    const float* aSrc = x + (size_t)rowidx[arow] * DIM + ahalf * 32;
    // ldmatrix per-thread base (within a stage): rows lane&15, col-half lane>>4
    const uint32_t ldsmOff = (uint32_t)((wm * 64 + (lane & 15)) * AROWB
                                        + (lane >> 4) * 16);

    for (int nc = 0; nc < NCHUNK; nc++) {
        float acc[4][6][4];
#pragma unroll
        for (int mt = 0; mt < 4; mt++)
#pragma unroll
            for (int nt = 0; nt < 6; nt++)
#pragma unroll
                for (int q = 0; q < 4; q++) acc[mt][nt][q] = 0.f;

        const uint4* bChunk = g_W1T + ((size_t)(e * NCHUNK + nc)) * NKC * 1536;

        // ---- prologue: stage chunk 0 into buffer 0 ----
        {
            const uint4* bs = bChunk + tid;
#pragma unroll
            for (int j = 0; j < 6; j++)
                cp_async16(bSmem0 + (tid + j * 256) * 16, bs + j * 256);
            CP_COMMIT();
            uint32_t* ad = (uint32_t*)(smem + SM_A) + arow * AST32 + ahalf * 16;
#pragma unroll
            for (int q = 0; q < 4; q++) {
                float4 fa = *(const float4*)(aSrc + q * 8);
                float4 fb = *(const float4*)(aSrc + q * 8 + 4);
                uint4 v = make_uint4(pack2(fa.x, fa.y), pack2(fa.z, fa.w),
                                     pack2(fb.x, fb.y), pack2(fb.z, fb.w));
                *(uint4*)(ad + q * 4) = v;
            }
        }

        // ---- main K loop ----
        for (int k = 0; k < NKC; k++) {
            const int cur = k & 1, nxt = cur ^ 1;
            CP_WAIT0();
            __syncthreads();

            // prefetch: B(k+1) via cp.async, A(k+1) LDGs issued now,
            // dependent pack+STS deferred until after compute.
            float4 f[8];
            const bool more = (k < NKC - 1);
            if (more) {
                const uint4* bs = bChunk + (size_t)(k + 1) * 1536 + tid;
#pragma unroll
                for (int j = 0; j < 6; j++)
                    cp_async16(bSmem0 + nxt * BBYTES + (tid + j * 256) * 16,
                               bs + j * 256);
                CP_COMMIT();
                const float4* as = (const float4*)(aSrc + (k + 1) * KC);
#pragma unroll
                for (int q = 0; q < 8; q++) f[q] = as[q];
            }

            // compute chunk k (K=64 = 4 ksteps of 16)
            const uint32_t aBase = sbase + SM_A + cur * ABYTES + ldsmOff;
            const uint4* Bs = (const uint4*)(smem + SM_B + cur * BBYTES);
#pragma unroll
            for (int ks = 0; ks < 4; ks++) {
                uint4 bf[3];
#pragma unroll
                for (int j = 0; j < 3; j++)
                    bf[j] = Bs[(ks * 12 + wn * 3 + j) * 32 + lane];
#pragma unroll
                for (int mt = 0; mt < 4; mt++) {
                    uint32_t af[4];
                    ldsm4(af, aBase + mt * (16 * AROWB) + ks * 32);
                    mma_f16(acc[mt][0], af, bf[0].x, bf[0].y);
                    mma_f16(acc[mt][1], af, bf[0].z, bf[0].w);
                    mma_f16(acc[mt][2], af, bf[1].x, bf[1].y);
                    mma_f16(acc[mt][3], af, bf[1].z, bf[1].w);
                    mma_f16(acc[mt][4], af, bf[2].x, bf[2].y);
                    mma_f16(acc[mt][5], af, bf[2].z, bf[2].w);
                }
            }

            if (more) {   // pack + stage A(k+1) (LDGs have had compute to land)
                uint32_t* ad = (uint32_t*)(smem + SM_A + nxt * ABYTES)
                               + arow * AST32 + ahalf * 16;
#pragma unroll
                for (int q = 0; q < 4; q++) {
                    uint4 v = make_uint4(
                        pack2(f[2 * q].x, f[2 * q].y),
                        pack2(f[2 * q].z, f[2 * q].w),
                        pack2(f[2 * q + 1].x, f[2 * q + 1].y),
                        pack2(f[2 * q + 1].z, f[2 * q + 1].w));
                    *(uint4*)(ad + q * 4) = v;
                }
            }
        }

        // ---- layer-2 partials from accumulators (fp32) ----
#pragma unroll
        for (int mt = 0; mt < 4; mt++) {
            float p[2][8];
#pragma unroll
            for (int rr = 0; rr < 2; rr++)
#pragma unroll
                for (int c = 0; c < 8; c++) p[rr][c] = 0.f;
#pragma unroll
            for (int nt = 0; nt < 6; nt++) {
                const int ng = nc * TILE_N + wn * 48 + nt * 8 + (lane & 3) * 2;
                const float bb0 = b1s[ng], bb1 = b1s[ng + 1];
                const float4* w0 = (const float4*)(w2s + ng * 8);
                const float4 wa0 = w0[0], wa1 = w0[1], wb0 = w0[2], wb1 = w0[3];
                const float h00 = fmaxf(acc[mt][nt][0] + bb0, 0.f);
                const float h01 = fmaxf(acc[mt][nt][1] + bb1, 0.f);
                const float h10 = fmaxf(acc[mt][nt][2] + bb0, 0.f);
                const float h11 = fmaxf(acc[mt][nt][3] + bb1, 0.f);
                p[0][0] = fmaf(h00, wa0.x, fmaf(h01, wb0.x, p[0][0]));
                p[0][1] = fmaf(h00, wa0.y, fmaf(h01, wb0.y, p[0][1]));
                p[0][2] = fmaf(h00, wa0.z, fmaf(h01, wb0.z, p[0][2]));
                p[0][3] = fmaf(h00, wa0.w, fmaf(h01, wb0.w, p[0][3]));
                p[0][4] = fmaf(h00, wa1.x, fmaf(h01, wb1.x, p[0][4]));
                p[0][5] = fmaf(h00, wa1.y, fmaf(h01, wb1.y, p[0][5]));
                p[0][6] = fmaf(h00, wa1.z, fmaf(h01, wb1.z, p[0][6]));
                p[0][7] = fmaf(h00, wa1.w, fmaf(h01, wb1.w, p[0][7]));
                p[1][0] = fmaf(h10, wa0.x, fmaf(h11, wb0.x, p[1][0]));
                p[1][1] = fmaf(h10, wa0.y, fmaf(h11, wb0.y, p[1][1]));
                p[1][2] = fmaf(h10, wa0.z, fmaf(h11, wb0.z, p[1][2]));
                p[1][3] = fmaf(h10, wa0.w, fmaf(h11, wb0.w, p[1][3]));
                p[1][4] = fmaf(h10, wa1.x, fmaf(h11, wb1.x, p[1][4]));
                p[1][5] = fmaf(h10, wa1.y, fmaf(h11, wb1.y, p[1][5]));
                p[1][6] = fmaf(h10, wa1.z, fmaf(h11, wb1.z, p[1][6]));
                p[1][7] = fmaf(h10, wa1.w, fmaf(h11, wb1.w, p[1][7]));
            }
#pragma unroll
            for (int rr = 0; rr < 2; rr++)
#pragma unroll
                for (int c = 0; c < 8; c++) {
                    float v = p[rr][c];
                    v += __shfl_xor_sync(0xffffffffu, v, 1);
                    v += __shfl_xor_sync(0xffffffffu, v, 2);
                    p[rr][c] = v;
                }
            if ((lane & 3) == 0) {
#pragma unroll
                for (int rr = 0; rr < 2; rr++) {
                    const int row = wm * 64 + mt * 16 + rr * 8 + (lane >> 2);
                    float* dst = lp + ((size_t)wn * TILE_M + row) * 8;
#pragma unroll
                    for (int c = 0; c < 8; c++) dst[c] += p[rr][c];
                }
            }
        }
    }

    // ---- combine n-warp partials + b2, scatter ----
    __syncthreads();
    if (tid < TILE_M && tid < cnt) {
        float o[8];
#pragma unroll
        for (int c = 0; c < 8; c++)
            o[c] = lp[(0 * TILE_M + tid) * 8 + c] + lp[(1 * TILE_M + tid) * 8 + c]
                 + lp[(2 * TILE_M + tid) * 8 + c] + lp[(3 * TILE_M + tid) * 8 + c]
                 + b2s[c];
        float4* dst = (float4*)(out + (size_t)rowidx[tid] * NCLS);
        dst[0] = make_float4(o[0], o[1], o[2], o[3]);
        dst[1] = make_float4(o[4], o[5], o[6], o[7]);
    }
}

// ---------------- launch ----------------
extern "C" void kernel_launch(void* const* d_in, const int* in_sizes, int n_in,
                              void* d_out, int out_size) {
    const float* x = nullptr;
    const float* W1 = nullptr;
    const float* b1 = nullptr;
    const float* W2 = nullptr;
    const float* b2 = nullptr;
    const int* qt = nullptr;
    for (int i = 0; i < n_in; i++) {
        switch (in_sizes[i]) {
            case NSAMP * DIM:       x  = (const float*)d_in[i]; break;
            case NEXP * DIM * HID:  W1 = (const float*)d_in[i]; break;
            case NEXP * HID:        b1 = (const float*)d_in[i]; break;
            case NEXP * HID * NCLS: W2 = (const float*)d_in[i]; break;
            case NEXP * NCLS:       b2 = (const float*)d_in[i]; break;
            case NSAMP:             qt = (const int*)d_in[i];   break;
            default: break;
        }
    }
    float* out = (float*)d_out;

    void* cntAddr = nullptr;
    cudaGetSymbolAddress(&cntAddr, g_cnt);
    cudaMemsetAsync(cntAddr, 0, sizeof(int) * 2 * NEXP, 0);

    k_hist<<<NSAMP / 256, 256>>>(qt);
    k_scatter<<<NSAMP / 256, 256>>>(qt);
    k_packW1<<<294912 / 256, 256>>>(W1);

    cudaFuncSetAttribute(k_moe, cudaFuncAttributeMaxDynamicSharedMemorySize,
                         SM_TOTAL);
    k_moe<<<GRID_TILES, THREADS, SM_TOTAL>>>(x, W2, b1, b2, out);
}